// round 4
// baseline (speedup 1.0000x reference)
#include <cuda_runtime.h>
#include <cuda_bf16.h>
#include <math.h>

// ---------------------------------------------------------------------------
// HawkBlock: B=4, T=2048, DIM=1024, HID=2048, GHID=2048, K=4
// Pipeline:
//   xn = rmsnorm(x, gamma1)
//   z  = xn @ W_in^T                        [M,4096]  gate=z[:,:2048], xcr=z[:,2048:]
//   xc = causal depthwise conv(xcr) + b     [M,2048]
//   g  = xc @ W_gates^T + b_gates           [M,4096]  forget=g[:,:2048], inp=g[:,2048:]
//   alpha = exp(-8*softplus(fb)*sigmoid(forget)); beta=sqrt(1-a^2+1e-6)
//   xs = beta*sigmoid(inp)*xc ; h = scan(alpha, xs)
//   gated = gelu(gate)*h ; x2 = x + gated @ W_out^T     -> d_out
//   xn2 = rmsnorm(x2, gamma2); gz = xn2 @ W_grow^T      [M,4096]
//   m = gelu(gz[:,:2048]) * gz[:,2048:]
//   out = x2 + m @ W_shrink^T                           -> d_out (accum)
// ---------------------------------------------------------------------------

#define BATCH 4
#define TLEN  2048
#define MROWS (BATCH * TLEN)   // 8192
#define DIM   1024
#define HID   2048
#define H2    4096
#define GHID  2048
#define KCONV 4
#define SEG   128
#define NSEG  (TLEN / SEG)     // 16

// ------------------------- scratch (static device) -------------------------
__device__ float g_xn[(size_t)MROWS * DIM];     // xn, later xn2
__device__ float g_z [(size_t)MROWS * H2];      // z (gate | xcr), P overwrites xcr half; later gz
__device__ float g_xc[(size_t)MROWS * HID];     // conv out; later mlp intermediate m
__device__ float g_g [(size_t)MROWS * H2];      // gates g
__device__ float g_h [(size_t)MROWS * HID];     // L, then gelu(gate)*h
__device__ float g_h0[(size_t)BATCH * NSEG * HID];

// ------------------------------ helpers ------------------------------------
__device__ __forceinline__ float sigmoidf_(float x) { return 1.f / (1.f + expf(-x)); }
__device__ __forceinline__ float gelu_exact(float x) {
    return 0.5f * x * (1.f + erff(x * 0.70710678118654752440f));
}

// ------------------------------ rmsnorm ------------------------------------
// one block per row, 256 threads, 4 floats each (DIM=1024)
__global__ void rmsnorm_kernel(const float* __restrict__ x,
                               const float* __restrict__ gamma,
                               float* __restrict__ out)
{
    const int row = blockIdx.x;
    const int tid = threadIdx.x;
    const float4 v = reinterpret_cast<const float4*>(x + (size_t)row * DIM)[tid];
    float ss = v.x*v.x + v.y*v.y + v.z*v.z + v.w*v.w;
    #pragma unroll
    for (int o = 16; o > 0; o >>= 1) ss += __shfl_xor_sync(0xffffffffu, ss, o);
    __shared__ float red[8];
    if ((tid & 31) == 0) red[tid >> 5] = ss;
    __syncthreads();
    float tot = red[0] + red[1] + red[2] + red[3] + red[4] + red[5] + red[6] + red[7];
    const float scale = sqrtf((float)DIM / tot);
    const float4 g = reinterpret_cast<const float4*>(gamma)[tid];
    float4 o4;
    o4.x = v.x * g.x * scale;
    o4.y = v.y * g.y * scale;
    o4.z = v.z * g.z * scale;
    o4.w = v.w * g.w * scale;
    reinterpret_cast<float4*>(out + (size_t)row * DIM)[tid] = o4;
}

// ------------------------------- SGEMM --------------------------------------
// C[M,N] = A[M,K] @ B[N,K]^T (+bias[N]) (+resid[M,N]); M%128==0, N%128==0, K%8==0
__global__ __launch_bounds__(256, 2)
void sgemm_tn(const float* __restrict__ A, const float* __restrict__ B,
              const float* __restrict__ bias, const float* __restrict__ resid,
              float* __restrict__ C, int M, int N, int K)
{
    __shared__ float As[8][132];
    __shared__ float Bs[8][132];

    const int tid  = threadIdx.x;
    const int lrow = tid >> 1;           // 0..127
    const int lk   = (tid & 1) << 2;     // 0 or 4
    const int bm   = blockIdx.y << 7;
    const int bn   = blockIdx.x << 7;

    const float* Ap = A + (size_t)(bm + lrow) * K + lk;
    const float* Bp = B + (size_t)(bn + lrow) * K + lk;

    const int mo = (tid >> 4) << 3;      // 0..120
    const int no = (tid & 15) << 3;      // 0..120

    float acc[8][8];
    #pragma unroll
    for (int i = 0; i < 8; i++)
        #pragma unroll
        for (int j = 0; j < 8; j++) acc[i][j] = 0.f;

    float4 a4 = *reinterpret_cast<const float4*>(Ap);
    float4 b4 = *reinterpret_cast<const float4*>(Bp);

    for (int k0 = 0; k0 < K; k0 += 8) {
        As[lk + 0][lrow] = a4.x; As[lk + 1][lrow] = a4.y;
        As[lk + 2][lrow] = a4.z; As[lk + 3][lrow] = a4.w;
        Bs[lk + 0][lrow] = b4.x; Bs[lk + 1][lrow] = b4.y;
        Bs[lk + 2][lrow] = b4.z; Bs[lk + 3][lrow] = b4.w;
        __syncthreads();

        if (k0 + 8 < K) {
            a4 = *reinterpret_cast<const float4*>(Ap + k0 + 8);
            b4 = *reinterpret_cast<const float4*>(Bp + k0 + 8);
        }

        #pragma unroll
        for (int kk = 0; kk < 8; kk++) {
            float ar[8], br[8];
            *reinterpret_cast<float4*>(&ar[0]) = *reinterpret_cast<const float4*>(&As[kk][mo]);
            *reinterpret_cast<float4*>(&ar[4]) = *reinterpret_cast<const float4*>(&As[kk][mo + 4]);
            *reinterpret_cast<float4*>(&br[0]) = *reinterpret_cast<const float4*>(&Bs[kk][no]);
            *reinterpret_cast<float4*>(&br[4]) = *reinterpret_cast<const float4*>(&Bs[kk][no + 4]);
            #pragma unroll
            for (int i = 0; i < 8; i++)
                #pragma unroll
                for (int j = 0; j < 8; j++)
                    acc[i][j] = fmaf(ar[i], br[j], acc[i][j]);
        }
        __syncthreads();
    }

    #pragma unroll
    for (int i = 0; i < 8; i++) {
        const size_t rowoff = (size_t)(bm + mo + i) * N + bn + no;
        #pragma unroll
        for (int j = 0; j < 8; j += 4) {
            float4 v;
            v.x = acc[i][j]; v.y = acc[i][j + 1]; v.z = acc[i][j + 2]; v.w = acc[i][j + 3];
            if (bias) {
                v.x += bias[bn + no + j];     v.y += bias[bn + no + j + 1];
                v.z += bias[bn + no + j + 2]; v.w += bias[bn + no + j + 3];
            }
            if (resid) {
                const float4 r = *reinterpret_cast<const float4*>(resid + rowoff + j);
                v.x += r.x; v.y += r.y; v.z += r.z; v.w += r.w;
            }
            *reinterpret_cast<float4*>(C + rowoff + j) = v;
        }
    }
}

// -------------------------- depthwise causal conv ---------------------------
__global__ void conv_kernel(const float* __restrict__ z,
                            const float* __restrict__ conv_w,
                            const float* __restrict__ conv_b,
                            float* __restrict__ out)
{
    const int idx = blockIdx.x * blockDim.x + threadIdx.x;  // over MROWS*HID
    const int c   = idx & (HID - 1);
    const int row = idx >> 11;                // /HID
    const int t   = row & (TLEN - 1);
    const float* zc = z + (size_t)row * H2 + HID + c;
    const float w0 = conv_w[c * KCONV + 0];
    const float w1 = conv_w[c * KCONV + 1];
    const float w2 = conv_w[c * KCONV + 2];
    const float w3 = conv_w[c * KCONV + 3];
    float acc = conv_b[c] + w3 * zc[0];
    if (t >= 1) acc = fmaf(w2, zc[-(ptrdiff_t)H2],      acc);
    if (t >= 2) acc = fmaf(w1, zc[-2 * (ptrdiff_t)H2],  acc);
    if (t >= 3) acc = fmaf(w0, zc[-3 * (ptrdiff_t)H2],  acc);
    out[(size_t)row * HID + c] = acc;
}

// --------------------------- scan phase 1 -----------------------------------
// per (b, seg, c): local scan L(t) with h0=0 and running product P(t).
// P(t) stored into z's xcr half (dead after conv); L(t) into g_h.
__global__ void scan_phase1(const float* __restrict__ g,
                            const float* __restrict__ xc,
                            const float* __restrict__ forget_base,
                            float* __restrict__ z_P,
                            float* __restrict__ L_out)
{
    const int idx = blockIdx.x * blockDim.x + threadIdx.x;  // over BATCH*NSEG*HID
    const int c   = idx & (HID - 1);
    const int seg = (idx >> 11) & (NSEG - 1);
    const int b   = idx >> 15;                // /(HID*NSEG)

    const float coef = -8.0f * log1pf(expf(forget_base[c]));  // ALPHA_LOG_SCALE * softplus
    float P = 1.f, L = 0.f;
    const size_t row0 = (size_t)b * TLEN + seg * SEG;
    for (int i = 0; i < SEG; i++) {
        const size_t row = row0 + i;
        const float f   = g[row * H2 + c];
        const float ip  = g[row * H2 + HID + c];
        const float xcv = xc[row * HID + c];
        const float alpha = expf(coef * sigmoidf_(f));
        const float beta  = sqrtf(1.f - alpha * alpha + 1e-6f);
        const float xs    = beta * sigmoidf_(ip) * xcv;
        P *= alpha;
        L = fmaf(alpha, L, xs);
        z_P[row * H2 + HID + c] = P;
        L_out[row * HID + c]    = L;
    }
}

// --------------------------- scan phase 2 -----------------------------------
// per (b, c): combine segment carries -> h0 per segment.
__global__ void scan_phase2(const float* __restrict__ z_P,
                            const float* __restrict__ L,
                            float* __restrict__ h0buf)
{
    const int idx = blockIdx.x * blockDim.x + threadIdx.x;  // over BATCH*HID
    const int c = idx & (HID - 1);
    const int b = idx >> 11;
    float h0 = 0.f;
    #pragma unroll
    for (int s = 0; s < NSEG; s++) {
        h0buf[((size_t)b * NSEG + s) * HID + c] = h0;
        const size_t last = (size_t)b * TLEN + s * SEG + (SEG - 1);
        h0 = fmaf(z_P[last * H2 + HID + c], h0, L[last * HID + c]);
    }
}

// --------------------- scan phase 3 (+ gelu(gate) * h) ----------------------
__global__ void scan_phase3(const float* __restrict__ z,
                            const float* __restrict__ h0buf,
                            float* __restrict__ hL)
{
    const int idx = blockIdx.x * blockDim.x + threadIdx.x;  // over MROWS*HID
    const int c   = idx & (HID - 1);
    const int row = idx >> 11;
    const int t   = row & (TLEN - 1);
    const int b   = row >> 11;                 // /TLEN
    const int seg = t >> 7;                    // /SEG
    const float L    = hL[idx];
    const float P    = z[(size_t)row * H2 + HID + c];
    const float h0   = h0buf[((size_t)b * NSEG + seg) * HID + c];
    const float h    = fmaf(P, h0, L);
    const float gate = z[(size_t)row * H2 + c];
    hL[idx] = gelu_exact(gate) * h;
}

// ---------------------------- MLP gating ------------------------------------
__global__ void mlp_gate_kernel(const float* __restrict__ gz, float* __restrict__ m)
{
    const int idx = blockIdx.x * blockDim.x + threadIdx.x;  // over MROWS*GHID
    const int c   = idx & (GHID - 1);
    const int row = idx >> 11;
    const float mg = gz[(size_t)row * H2 + c];
    const float mx = gz[(size_t)row * H2 + GHID + c];
    m[idx] = gelu_exact(mg) * mx;
}

// ------------------------------ launcher ------------------------------------
extern "C" void kernel_launch(void* const* d_in, const int* in_sizes, int n_in,
                              void* d_out, int out_size)
{
    const float* x           = (const float*)d_in[0];
    const float* W_in        = (const float*)d_in[1];
    const float* conv_w      = (const float*)d_in[2];
    const float* conv_b      = (const float*)d_in[3];
    const float* W_gates     = (const float*)d_in[4];
    const float* b_gates     = (const float*)d_in[5];
    const float* forget_base = (const float*)d_in[6];
    const float* W_out       = (const float*)d_in[7];
    const float* gamma1      = (const float*)d_in[8];
    const float* gamma2      = (const float*)d_in[9];
    const float* W_grow      = (const float*)d_in[10];
    const float* W_shrink    = (const float*)d_in[11];
    float* out = (float*)d_out;

    float *pxn, *pz, *pxc, *pg, *ph, *ph0;
    cudaGetSymbolAddress((void**)&pxn, g_xn);
    cudaGetSymbolAddress((void**)&pz,  g_z);
    cudaGetSymbolAddress((void**)&pxc, g_xc);
    cudaGetSymbolAddress((void**)&pg,  g_g);
    cudaGetSymbolAddress((void**)&ph,  g_h);
    cudaGetSymbolAddress((void**)&ph0, g_h0);

    const dim3 blk(256);

    // 1. xn = rmsnorm(x, gamma1)
    rmsnorm_kernel<<<MROWS, blk>>>(x, gamma1, pxn);

    // 2. z = xn @ W_in^T   [8192,4096]
    sgemm_tn<<<dim3(H2 / 128, MROWS / 128), blk>>>(pxn, W_in, nullptr, nullptr, pz,
                                                   MROWS, H2, DIM);

    // 3. xc = depthwise causal conv + bias
    conv_kernel<<<(MROWS * HID) / 256, blk>>>(pz, conv_w, conv_b, pxc);

    // 4. g = xc @ W_gates^T + b_gates   [8192,4096]
    sgemm_tn<<<dim3(H2 / 128, MROWS / 128), blk>>>(pxc, W_gates, b_gates, nullptr, pg,
                                                   MROWS, H2, HID);

    // 5. chunked linear recurrence
    scan_phase1<<<(BATCH * NSEG * HID) / 256, blk>>>(pg, pxc, forget_base, pz, ph);
    scan_phase2<<<(BATCH * HID) / 256, blk>>>(pz, ph, ph0);
    scan_phase3<<<(MROWS * HID) / 256, blk>>>(pz, ph0, ph);

    // 6. x2 = x + (gelu(gate)*h) @ W_out^T  -> d_out
    sgemm_tn<<<dim3(DIM / 128, MROWS / 128), blk>>>(ph, W_out, nullptr, x, out,
                                                    MROWS, DIM, HID);

    // 7. xn2 = rmsnorm(x2, gamma2)
    rmsnorm_kernel<<<MROWS, blk>>>(out, gamma2, pxn);

    // 8. gz = xn2 @ W_grow^T   [8192,4096]
    sgemm_tn<<<dim3(H2 / 128, MROWS / 128), blk>>>(pxn, W_grow, nullptr, nullptr, pz,
                                                   MROWS, H2, DIM);

    // 9. m = gelu(mgate) * mx
    mlp_gate_kernel<<<(MROWS * GHID) / 256, blk>>>(pz, pxc);

    // 10. out = x2 + m @ W_shrink^T  (accumulate into d_out)
    sgemm_tn<<<dim3(DIM / 128, MROWS / 128), blk>>>(pxc, W_shrink, nullptr, out, out,
                                                    MROWS, DIM, HID);
}

// round 16
// speedup vs baseline: 2.5116x; 2.5116x over previous
#include <cuda_runtime.h>
#include <cuda_bf16.h>
#include <math.h>
#include <stdint.h>

// ---------------------------------------------------------------------------
// HawkBlock with mma.sync (HMMA) bf16 split-precision GEMMs.
//   C = Ahi*Bhi + Ahi*Blo + Alo*Bhi  (bf16 in, fp32 accumulate)
// compute_103-baseline features only (no tcgen05 / TMEM / 'a'-suffix PTX).
// CTA tile 128x128, KC=32, 8 warps x (64x32), smem pitch 80B (ldmatrix
// conflict-free), 2 CTAs/SM for fill/MMA overlap.
// R15 fix: B-fragment pairing is {bf[2*ni], bf[2*ni+1]} (same n-block,
// k-halves 0-7/8-15); previous round paired b0 of adjacent n-blocks.
// ---------------------------------------------------------------------------

#define BATCH 4
#define TLEN  2048
#define MROWS (BATCH * TLEN)   // 8192
#define DIM   1024
#define HID   2048
#define H2    4096
#define GHID  2048
#define KCONV 4
#define SEG   128
#define NSEG  (TLEN / SEG)     // 16

#define TM 128
#define TN 128
#define KC 32
#define PITCH 40               // bf16 elems per smem row (32 data + 8 pad) = 80B
#define TILE_ELEMS (128 * PITCH)

// ------------------------- scratch (static device) -------------------------
__device__ float g_xn[(size_t)MROWS * DIM];
__device__ float g_z [(size_t)MROWS * H2];
__device__ float g_xc[(size_t)MROWS * HID];
__device__ float g_g [(size_t)MROWS * H2];
__device__ float g_h [(size_t)MROWS * HID];
__device__ float g_h0[(size_t)BATCH * NSEG * HID];

// ------------------------------ PTX helpers ---------------------------------
__device__ __forceinline__ uint32_t smem_u32(const void* p) {
    uint32_t a;
    asm("{ .reg .u64 t; cvta.to.shared.u64 t, %1; cvt.u32.u64 %0, t; }"
        : "=r"(a) : "l"(p));
    return a;
}

__device__ __forceinline__ void ldm_x4(uint32_t& r0, uint32_t& r1,
                                       uint32_t& r2, uint32_t& r3, uint32_t addr) {
    asm volatile("ldmatrix.sync.aligned.m8n8.x4.shared.b16 {%0,%1,%2,%3}, [%4];"
                 : "=r"(r0), "=r"(r1), "=r"(r2), "=r"(r3) : "r"(addr));
}

__device__ __forceinline__ void mma16816(float* c, uint32_t a0, uint32_t a1,
                                         uint32_t a2, uint32_t a3,
                                         uint32_t b0, uint32_t b1) {
    asm volatile(
        "mma.sync.aligned.m16n8k16.row.col.f32.bf16.bf16.f32 "
        "{%0,%1,%2,%3}, {%4,%5,%6,%7}, {%8,%9}, {%0,%1,%2,%3};"
        : "+f"(c[0]), "+f"(c[1]), "+f"(c[2]), "+f"(c[3])
        : "r"(a0), "r"(a1), "r"(a2), "r"(a3), "r"(b0), "r"(b1));
}

// fp32x4 -> bf16 hi/lo, store 8B each into pitch-80 conflict-free smem rows
__device__ __forceinline__ void cvt_store(__nv_bfloat16* hiT, __nv_bfloat16* loT,
                                          int r, int g, float4 v) {
    __nv_bfloat16 h0 = __float2bfloat16(v.x);
    __nv_bfloat16 h1 = __float2bfloat16(v.y);
    __nv_bfloat16 h2 = __float2bfloat16(v.z);
    __nv_bfloat16 h3 = __float2bfloat16(v.w);
    __nv_bfloat16 l0 = __float2bfloat16(v.x - __bfloat162float(h0));
    __nv_bfloat16 l1 = __float2bfloat16(v.y - __bfloat162float(h1));
    __nv_bfloat16 l2 = __float2bfloat16(v.z - __bfloat162float(h2));
    __nv_bfloat16 l3 = __float2bfloat16(v.w - __bfloat162float(h3));
    uint2 hv, lv;
    hv.x = ((uint32_t)__bfloat16_as_ushort(h1) << 16) | __bfloat16_as_ushort(h0);
    hv.y = ((uint32_t)__bfloat16_as_ushort(h3) << 16) | __bfloat16_as_ushort(h2);
    lv.x = ((uint32_t)__bfloat16_as_ushort(l1) << 16) | __bfloat16_as_ushort(l0);
    lv.y = ((uint32_t)__bfloat16_as_ushort(l3) << 16) | __bfloat16_as_ushort(l2);
    *reinterpret_cast<uint2*>(hiT + r * PITCH + g * 4) = hv;
    *reinterpret_cast<uint2*>(loT + r * PITCH + g * 4) = lv;
}

// ------------------------- mma.sync GEMM -------------------------------------
// C[M,N] = A[M,K] @ B[N,K]^T (+bias[N]) (+resid[M,N]); M%128==0, N%128==0, K%32==0
__global__ __launch_bounds__(256, 2)
void mma_gemm(const float* __restrict__ A, const float* __restrict__ B,
              const float* __restrict__ bias, const float* __restrict__ resid,
              float* __restrict__ C, int M, int N, int K)
{
    __shared__ __align__(16) __nv_bfloat16 smem[4 * TILE_ELEMS];
    __nv_bfloat16* sAh = smem;
    __nv_bfloat16* sAl = smem + TILE_ELEMS;
    __nv_bfloat16* sBh = smem + 2 * TILE_ELEMS;
    __nv_bfloat16* sBl = smem + 3 * TILE_ELEMS;

    const int tid  = threadIdx.x;
    const int wid  = tid >> 5;
    const int lane = tid & 31;
    const int bm   = blockIdx.y * TM;
    const int bn   = blockIdx.x * TN;
    const int wm   = (wid & 1) * 64;    // warp M offset within tile
    const int wn   = (wid >> 1) * 32;   // warp N offset within tile

    float acc[4][4][4];
    #pragma unroll
    for (int i = 0; i < 4; i++)
        #pragma unroll
        for (int j = 0; j < 4; j++)
            #pragma unroll
            for (int k = 0; k < 4; k++) acc[i][j][k] = 0.f;

    // fill mapping: each thread loads rows (tid>>3)+{0,32,64,96}, group g=(tid&7)
    const int fr = tid >> 3;
    const int fg = tid & 7;
    const float* Ab = A + (size_t)(bm + fr) * K + fg * 4;
    const float* Bb = B + (size_t)(bn + fr) * K + fg * 4;

    // ldmatrix per-lane byte offsets
    // A: lanes 0-15 -> rows 0-15 col-byte 0; lanes 16-31 -> rows 0-15 col-byte 16
    //    => regs r0..r3 = a0..a3 of m16n8k16 row-major A fragment.
    // B: lanes 0-7 n0-7/k0-7, 8-15 n0-7/k8-15, 16-23 n8-15/k0-7, 24-31 n8-15/k8-15
    //    => regs = {b0(n0-7), b1(n0-7), b0(n8-15), b1(n8-15)}.
    const uint32_t smb = smem_u32(smem);
    const uint32_t aOff = (uint32_t)((lane & 15) * (PITCH * 2) + (lane >> 4) * 16);
    const int bN  = (lane & 7) + ((lane >> 4) * 8);
    const uint32_t bOff = (uint32_t)(bN * (PITCH * 2) + ((lane >> 3) & 1) * 16);
    const uint32_t aBaseH = smb + (uint32_t)(wm * (PITCH * 2)) + aOff;
    const uint32_t aBaseL = aBaseH + TILE_ELEMS * 2;
    const uint32_t bBaseH = smb + 2u * TILE_ELEMS * 2 + (uint32_t)(wn * (PITCH * 2)) + bOff;
    const uint32_t bBaseL = bBaseH + TILE_ELEMS * 2;

    const int NC = K / KC;
    for (int c = 0; c < NC; c++) {
        // ---- fill: LDG.128 fp32 -> bf16 hi/lo -> STS ----
        float4 av[4], bv[4];
        #pragma unroll
        for (int i = 0; i < 4; i++)
            av[i] = *reinterpret_cast<const float4*>(Ab + (size_t)(i * 32) * K + c * KC);
        #pragma unroll
        for (int i = 0; i < 4; i++)
            bv[i] = *reinterpret_cast<const float4*>(Bb + (size_t)(i * 32) * K + c * KC);
        __syncthreads();   // previous chunk's ldmatrix done before overwrite
        #pragma unroll
        for (int i = 0; i < 4; i++) cvt_store(sAh, sAl, fr + i * 32, fg, av[i]);
        #pragma unroll
        for (int i = 0; i < 4; i++) cvt_store(sBh, sBl, fr + i * 32, fg, bv[i]);
        __syncthreads();

        // ---- MMA: 3 combos x 2 k16-steps x 16 mma ----
        #pragma unroll
        for (int combo = 0; combo < 3; combo++) {
            const uint32_t aB = (combo == 2) ? aBaseL : aBaseH;
            const uint32_t bB = (combo == 1) ? bBaseL : bBaseH;
            #pragma unroll
            for (int ks = 0; ks < 2; ks++) {
                uint32_t af[4][4];
                #pragma unroll
                for (int mi = 0; mi < 4; mi++)
                    ldm_x4(af[mi][0], af[mi][1], af[mi][2], af[mi][3],
                           aB + (uint32_t)(mi * 16 * (PITCH * 2)) + ks * 32);
                uint32_t bf[8];
                #pragma unroll
                for (int nh = 0; nh < 2; nh++)
                    ldm_x4(bf[nh * 4 + 0], bf[nh * 4 + 1], bf[nh * 4 + 2], bf[nh * 4 + 3],
                           bB + (uint32_t)(nh * 16 * (PITCH * 2)) + ks * 32);
                #pragma unroll
                for (int mi = 0; mi < 4; mi++)
                    #pragma unroll
                    for (int ni = 0; ni < 4; ni++)
                        mma16816(acc[mi][ni],
                                 af[mi][0], af[mi][1], af[mi][2], af[mi][3],
                                 bf[ni * 2], bf[ni * 2 + 1]);
            }
        }
    }

    // ---- epilogue ----
    // acc[mi][ni]: c0=C[m][n], c1=C[m][n+1], c2=C[m+8][n], c3=C[m+8][n+1]
    // m = bm+wm+mi*16+(lane>>2), n = bn+wn+ni*8+(lane&3)*2
    #pragma unroll
    for (int mi = 0; mi < 4; mi++) {
        const int m0 = bm + wm + mi * 16 + (lane >> 2);
        #pragma unroll
        for (int half = 0; half < 2; half++) {
            const size_t row = (size_t)(m0 + half * 8) * N;
            #pragma unroll
            for (int ni = 0; ni < 4; ni++) {
                const int n0 = bn + wn + ni * 8 + (lane & 3) * 2;
                float2 v;
                v.x = acc[mi][ni][half * 2 + 0];
                v.y = acc[mi][ni][half * 2 + 1];
                if (bias) { v.x += bias[n0]; v.y += bias[n0 + 1]; }
                if (resid) {
                    const float2 r = *reinterpret_cast<const float2*>(resid + row + n0);
                    v.x += r.x; v.y += r.y;
                }
                *reinterpret_cast<float2*>(C + row + n0) = v;
            }
        }
    }
}

// ------------------------------ helpers ------------------------------------
__device__ __forceinline__ float sigmoidf_(float x) { return 1.f / (1.f + expf(-x)); }
__device__ __forceinline__ float gelu_exact(float x) {
    return 0.5f * x * (1.f + erff(x * 0.70710678118654752440f));
}

// ------------------------------ rmsnorm ------------------------------------
__global__ void rmsnorm_kernel(const float* __restrict__ x,
                               const float* __restrict__ gamma,
                               float* __restrict__ out)
{
    const int row = blockIdx.x;
    const int tid = threadIdx.x;
    const float4 v = reinterpret_cast<const float4*>(x + (size_t)row * DIM)[tid];
    float ss = v.x*v.x + v.y*v.y + v.z*v.z + v.w*v.w;
    #pragma unroll
    for (int o = 16; o > 0; o >>= 1) ss += __shfl_xor_sync(0xffffffffu, ss, o);
    __shared__ float red[8];
    if ((tid & 31) == 0) red[tid >> 5] = ss;
    __syncthreads();
    float tot = red[0] + red[1] + red[2] + red[3] + red[4] + red[5] + red[6] + red[7];
    const float scale = sqrtf((float)DIM / tot);
    const float4 g = reinterpret_cast<const float4*>(gamma)[tid];
    float4 o4;
    o4.x = v.x * g.x * scale;
    o4.y = v.y * g.y * scale;
    o4.z = v.z * g.z * scale;
    o4.w = v.w * g.w * scale;
    reinterpret_cast<float4*>(out + (size_t)row * DIM)[tid] = o4;
}

// -------------------------- depthwise causal conv ---------------------------
__global__ void conv_kernel(const float* __restrict__ z,
                            const float* __restrict__ conv_w,
                            const float* __restrict__ conv_b,
                            float* __restrict__ out)
{
    const int idx = blockIdx.x * blockDim.x + threadIdx.x;
    const int c   = idx & (HID - 1);
    const int row = idx >> 11;
    const int t   = row & (TLEN - 1);
    const float* zc = z + (size_t)row * H2 + HID + c;
    const float w0 = conv_w[c * KCONV + 0];
    const float w1 = conv_w[c * KCONV + 1];
    const float w2 = conv_w[c * KCONV + 2];
    const float w3 = conv_w[c * KCONV + 3];
    float acc = conv_b[c] + w3 * zc[0];
    if (t >= 1) acc = fmaf(w2, zc[-(ptrdiff_t)H2],      acc);
    if (t >= 2) acc = fmaf(w1, zc[-2 * (ptrdiff_t)H2],  acc);
    if (t >= 3) acc = fmaf(w0, zc[-3 * (ptrdiff_t)H2],  acc);
    out[(size_t)row * HID + c] = acc;
}

// --------------------------- scan phase 1 -----------------------------------
__global__ void scan_phase1(const float* __restrict__ g,
                            const float* __restrict__ xc,
                            const float* __restrict__ forget_base,
                            float* __restrict__ z_P,
                            float* __restrict__ L_out)
{
    const int idx = blockIdx.x * blockDim.x + threadIdx.x;
    const int c   = idx & (HID - 1);
    const int seg = (idx >> 11) & (NSEG - 1);
    const int b   = idx >> 15;

    const float coef = -8.0f * log1pf(expf(forget_base[c]));
    float P = 1.f, L = 0.f;
    const size_t row0 = (size_t)b * TLEN + seg * SEG;
    for (int i = 0; i < SEG; i++) {
        const size_t row = row0 + i;
        const float f   = g[row * H2 + c];
        const float ip  = g[row * H2 + HID + c];
        const float xcv = xc[row * HID + c];
        const float alpha = expf(coef * sigmoidf_(f));
        const float beta  = sqrtf(1.f - alpha * alpha + 1e-6f);
        const float xs    = beta * sigmoidf_(ip) * xcv;
        P *= alpha;
        L = fmaf(alpha, L, xs);
        z_P[row * H2 + HID + c] = P;
        L_out[row * HID + c]    = L;
    }
}

// --------------------------- scan phase 2 -----------------------------------
__global__ void scan_phase2(const float* __restrict__ z_P,
                            const float* __restrict__ L,
                            float* __restrict__ h0buf)
{
    const int idx = blockIdx.x * blockDim.x + threadIdx.x;
    const int c = idx & (HID - 1);
    const int b = idx >> 11;
    float h0 = 0.f;
    #pragma unroll
    for (int s = 0; s < NSEG; s++) {
        h0buf[((size_t)b * NSEG + s) * HID + c] = h0;
        const size_t last = (size_t)b * TLEN + s * SEG + (SEG - 1);
        h0 = fmaf(z_P[last * H2 + HID + c], h0, L[last * HID + c]);
    }
}

// --------------------- scan phase 3 (+ gelu(gate) * h) ----------------------
__global__ void scan_phase3(const float* __restrict__ z,
                            const float* __restrict__ h0buf,
                            float* __restrict__ hL)
{
    const int idx = blockIdx.x * blockDim.x + threadIdx.x;
    const int c   = idx & (HID - 1);
    const int row = idx >> 11;
    const int t   = row & (TLEN - 1);
    const int b   = row >> 11;
    const int seg = t >> 7;
    const float L    = hL[idx];
    const float P    = z[(size_t)row * H2 + HID + c];
    const float h0   = h0buf[((size_t)b * NSEG + seg) * HID + c];
    const float h    = fmaf(P, h0, L);
    const float gate = z[(size_t)row * H2 + c];
    hL[idx] = gelu_exact(gate) * h;
}

// ---------------------------- MLP gating ------------------------------------
__global__ void mlp_gate_kernel(const float* __restrict__ gz, float* __restrict__ m)
{
    const int idx = blockIdx.x * blockDim.x + threadIdx.x;
    const int c   = idx & (GHID - 1);
    const int row = idx >> 11;
    const float mg = gz[(size_t)row * H2 + c];
    const float mx = gz[(size_t)row * H2 + GHID + c];
    m[idx] = gelu_exact(mg) * mx;
}

// ------------------------------ launcher ------------------------------------
extern "C" void kernel_launch(void* const* d_in, const int* in_sizes, int n_in,
                              void* d_out, int out_size)
{
    const float* x           = (const float*)d_in[0];
    const float* W_in        = (const float*)d_in[1];
    const float* conv_w      = (const float*)d_in[2];
    const float* conv_b      = (const float*)d_in[3];
    const float* W_gates     = (const float*)d_in[4];
    const float* b_gates     = (const float*)d_in[5];
    const float* forget_base = (const float*)d_in[6];
    const float* W_out       = (const float*)d_in[7];
    const float* gamma1      = (const float*)d_in[8];
    const float* gamma2      = (const float*)d_in[9];
    const float* W_grow      = (const float*)d_in[10];
    const float* W_shrink    = (const float*)d_in[11];
    float* out = (float*)d_out;

    float *pxn, *pz, *pxc, *pg, *ph, *ph0;
    cudaGetSymbolAddress((void**)&pxn, g_xn);
    cudaGetSymbolAddress((void**)&pz,  g_z);
    cudaGetSymbolAddress((void**)&pxc, g_xc);
    cudaGetSymbolAddress((void**)&pg,  g_g);
    cudaGetSymbolAddress((void**)&ph,  g_h);
    cudaGetSymbolAddress((void**)&ph0, g_h0);

    const dim3 blk(256);

    // 1. xn = rmsnorm(x, gamma1)
    rmsnorm_kernel<<<MROWS, blk>>>(x, gamma1, pxn);

    // 2. z = xn @ W_in^T   [8192,4096]
    mma_gemm<<<dim3(H2 / TN, MROWS / TM), blk>>>(pxn, W_in, nullptr, nullptr, pz,
                                                 MROWS, H2, DIM);

    // 3. xc = depthwise causal conv + bias
    conv_kernel<<<(MROWS * HID) / 256, blk>>>(pz, conv_w, conv_b, pxc);

    // 4. g = xc @ W_gates^T + b_gates   [8192,4096]
    mma_gemm<<<dim3(H2 / TN, MROWS / TM), blk>>>(pxc, W_gates, b_gates, nullptr, pg,
                                                 MROWS, H2, HID);

    // 5. chunked linear recurrence
    scan_phase1<<<(BATCH * NSEG * HID) / 256, blk>>>(pg, pxc, forget_base, pz, ph);
    scan_phase2<<<(BATCH * HID) / 256, blk>>>(pz, ph, ph0);
    scan_phase3<<<(MROWS * HID) / 256, blk>>>(pz, ph0, ph);

    // 6. x2 = x + (gelu(gate)*h) @ W_out^T  -> d_out
    mma_gemm<<<dim3(DIM / TN, MROWS / TM), blk>>>(ph, W_out, nullptr, x, out,
                                                  MROWS, DIM, HID);

    // 7. xn2 = rmsnorm(x2, gamma2)
    rmsnorm_kernel<<<MROWS, blk>>>(out, gamma2, pxn);

    // 8. gz = xn2 @ W_grow^T   [8192,4096]
    mma_gemm<<<dim3(H2 / TN, MROWS / TM), blk>>>(pxn, W_grow, nullptr, nullptr, pz,
                                                 MROWS, H2, DIM);

    // 9. m = gelu(mgate) * mx
    mlp_gate_kernel<<<(MROWS * GHID) / 256, blk>>>(pz, pxc);

    // 10. out = x2 + m @ W_shrink^T  (accumulate into d_out)
    mma_gemm<<<dim3(DIM / TN, MROWS / TM), blk>>>(pxc, W_shrink, nullptr, out, out,
                                                  MROWS, DIM, HID);
}

// round 17
// speedup vs baseline: 2.5145x; 1.0011x over previous
#include <cuda_runtime.h>
#include <cuda_bf16.h>
#include <math.h>
#include <stdint.h>

// ---------------------------------------------------------------------------
// HawkBlock with mma.sync (HMMA) bf16 split-precision GEMMs.
//   C = Ahi*Bhi + Ahi*Blo + Alo*Bhi  (bf16 in, fp32 accumulate)
// compute_103-baseline features only (no tcgen05 / TMEM / 'a'-suffix PTX).
// CTA tile 128x128, KC=32, 8 warps x (64x32), smem pitch 80B (ldmatrix
// conflict-free), 2 CTAs/SM for fill/MMA overlap.
// R15 fix: B-fragment pairing is {bf[2*ni], bf[2*ni+1]} (same n-block,
// k-halves 0-7/8-15); previous round paired b0 of adjacent n-blocks.
// ---------------------------------------------------------------------------

#define BATCH 4
#define TLEN  2048
#define MROWS (BATCH * TLEN)   // 8192
#define DIM   1024
#define HID   2048
#define H2    4096
#define GHID  2048
#define KCONV 4
#define SEG   128
#define NSEG  (TLEN / SEG)     // 16

#define TM 128
#define TN 128
#define KC 32
#define PITCH 40               // bf16 elems per smem row (32 data + 8 pad) = 80B
#define TILE_ELEMS (128 * PITCH)

// ------------------------- scratch (static device) -------------------------
__device__ float g_xn[(size_t)MROWS * DIM];
__device__ float g_z [(size_t)MROWS * H2];
__device__ float g_xc[(size_t)MROWS * HID];
__device__ float g_g [(size_t)MROWS * H2];
__device__ float g_h [(size_t)MROWS * HID];
__device__ float g_h0[(size_t)BATCH * NSEG * HID];

// ------------------------------ PTX helpers ---------------------------------
__device__ __forceinline__ uint32_t smem_u32(const void* p) {
    uint32_t a;
    asm("{ .reg .u64 t; cvta.to.shared.u64 t, %1; cvt.u32.u64 %0, t; }"
        : "=r"(a) : "l"(p));
    return a;
}

__device__ __forceinline__ void ldm_x4(uint32_t& r0, uint32_t& r1,
                                       uint32_t& r2, uint32_t& r3, uint32_t addr) {
    asm volatile("ldmatrix.sync.aligned.m8n8.x4.shared.b16 {%0,%1,%2,%3}, [%4];"
                 : "=r"(r0), "=r"(r1), "=r"(r2), "=r"(r3) : "r"(addr));
}

__device__ __forceinline__ void mma16816(float* c, uint32_t a0, uint32_t a1,
                                         uint32_t a2, uint32_t a3,
                                         uint32_t b0, uint32_t b1) {
    asm volatile(
        "mma.sync.aligned.m16n8k16.row.col.f32.bf16.bf16.f32 "
        "{%0,%1,%2,%3}, {%4,%5,%6,%7}, {%8,%9}, {%0,%1,%2,%3};"
        : "+f"(c[0]), "+f"(c[1]), "+f"(c[2]), "+f"(c[3])
        : "r"(a0), "r"(a1), "r"(a2), "r"(a3), "r"(b0), "r"(b1));
}

// fp32x4 -> bf16 hi/lo, store 8B each into pitch-80 conflict-free smem rows
__device__ __forceinline__ void cvt_store(__nv_bfloat16* hiT, __nv_bfloat16* loT,
                                          int r, int g, float4 v) {
    __nv_bfloat16 h0 = __float2bfloat16(v.x);
    __nv_bfloat16 h1 = __float2bfloat16(v.y);
    __nv_bfloat16 h2 = __float2bfloat16(v.z);
    __nv_bfloat16 h3 = __float2bfloat16(v.w);
    __nv_bfloat16 l0 = __float2bfloat16(v.x - __bfloat162float(h0));
    __nv_bfloat16 l1 = __float2bfloat16(v.y - __bfloat162float(h1));
    __nv_bfloat16 l2 = __float2bfloat16(v.z - __bfloat162float(h2));
    __nv_bfloat16 l3 = __float2bfloat16(v.w - __bfloat162float(h3));
    uint2 hv, lv;
    hv.x = ((uint32_t)__bfloat16_as_ushort(h1) << 16) | __bfloat16_as_ushort(h0);
    hv.y = ((uint32_t)__bfloat16_as_ushort(h3) << 16) | __bfloat16_as_ushort(h2);
    lv.x = ((uint32_t)__bfloat16_as_ushort(l1) << 16) | __bfloat16_as_ushort(l0);
    lv.y = ((uint32_t)__bfloat16_as_ushort(l3) << 16) | __bfloat16_as_ushort(l2);
    *reinterpret_cast<uint2*>(hiT + r * PITCH + g * 4) = hv;
    *reinterpret_cast<uint2*>(loT + r * PITCH + g * 4) = lv;
}

// ------------------------- mma.sync GEMM -------------------------------------
// C[M,N] = A[M,K] @ B[N,K]^T (+bias[N]) (+resid[M,N]); M%128==0, N%128==0, K%32==0
__global__ __launch_bounds__(256, 2)
void mma_gemm(const float* __restrict__ A, const float* __restrict__ B,
              const float* __restrict__ bias, const float* __restrict__ resid,
              float* __restrict__ C, int M, int N, int K)
{
    __shared__ __align__(16) __nv_bfloat16 smem[4 * TILE_ELEMS];
    __nv_bfloat16* sAh = smem;
    __nv_bfloat16* sAl = smem + TILE_ELEMS;
    __nv_bfloat16* sBh = smem + 2 * TILE_ELEMS;
    __nv_bfloat16* sBl = smem + 3 * TILE_ELEMS;

    const int tid  = threadIdx.x;
    const int wid  = tid >> 5;
    const int lane = tid & 31;
    const int bm   = blockIdx.y * TM;
    const int bn   = blockIdx.x * TN;
    const int wm   = (wid & 1) * 64;    // warp M offset within tile
    const int wn   = (wid >> 1) * 32;   // warp N offset within tile

    float acc[4][4][4];
    #pragma unroll
    for (int i = 0; i < 4; i++)
        #pragma unroll
        for (int j = 0; j < 4; j++)
            #pragma unroll
            for (int k = 0; k < 4; k++) acc[i][j][k] = 0.f;

    // fill mapping: each thread loads rows (tid>>3)+{0,32,64,96}, group g=(tid&7)
    const int fr = tid >> 3;
    const int fg = tid & 7;
    const float* Ab = A + (size_t)(bm + fr) * K + fg * 4;
    const float* Bb = B + (size_t)(bn + fr) * K + fg * 4;

    // ldmatrix per-lane byte offsets
    // A: lanes 0-15 -> rows 0-15 col-byte 0; lanes 16-31 -> rows 0-15 col-byte 16
    //    => regs r0..r3 = a0..a3 of m16n8k16 row-major A fragment.
    // B: lanes 0-7 n0-7/k0-7, 8-15 n0-7/k8-15, 16-23 n8-15/k0-7, 24-31 n8-15/k8-15
    //    => regs = {b0(n0-7), b1(n0-7), b0(n8-15), b1(n8-15)}.
    const uint32_t smb = smem_u32(smem);
    const uint32_t aOff = (uint32_t)((lane & 15) * (PITCH * 2) + (lane >> 4) * 16);
    const int bN  = (lane & 7) + ((lane >> 4) * 8);
    const uint32_t bOff = (uint32_t)(bN * (PITCH * 2) + ((lane >> 3) & 1) * 16);
    const uint32_t aBaseH = smb + (uint32_t)(wm * (PITCH * 2)) + aOff;
    const uint32_t aBaseL = aBaseH + TILE_ELEMS * 2;
    const uint32_t bBaseH = smb + 2u * TILE_ELEMS * 2 + (uint32_t)(wn * (PITCH * 2)) + bOff;
    const uint32_t bBaseL = bBaseH + TILE_ELEMS * 2;

    const int NC = K / KC;
    for (int c = 0; c < NC; c++) {
        // ---- fill: LDG.128 fp32 -> bf16 hi/lo -> STS ----
        float4 av[4], bv[4];
        #pragma unroll
        for (int i = 0; i < 4; i++)
            av[i] = *reinterpret_cast<const float4*>(Ab + (size_t)(i * 32) * K + c * KC);
        #pragma unroll
        for (int i = 0; i < 4; i++)
            bv[i] = *reinterpret_cast<const float4*>(Bb + (size_t)(i * 32) * K + c * KC);
        __syncthreads();   // previous chunk's ldmatrix done before overwrite
        #pragma unroll
        for (int i = 0; i < 4; i++) cvt_store(sAh, sAl, fr + i * 32, fg, av[i]);
        #pragma unroll
        for (int i = 0; i < 4; i++) cvt_store(sBh, sBl, fr + i * 32, fg, bv[i]);
        __syncthreads();

        // ---- MMA: 3 combos x 2 k16-steps x 16 mma ----
        #pragma unroll
        for (int combo = 0; combo < 3; combo++) {
            const uint32_t aB = (combo == 2) ? aBaseL : aBaseH;
            const uint32_t bB = (combo == 1) ? bBaseL : bBaseH;
            #pragma unroll
            for (int ks = 0; ks < 2; ks++) {
                uint32_t af[4][4];
                #pragma unroll
                for (int mi = 0; mi < 4; mi++)
                    ldm_x4(af[mi][0], af[mi][1], af[mi][2], af[mi][3],
                           aB + (uint32_t)(mi * 16 * (PITCH * 2)) + ks * 32);
                uint32_t bf[8];
                #pragma unroll
                for (int nh = 0; nh < 2; nh++)
                    ldm_x4(bf[nh * 4 + 0], bf[nh * 4 + 1], bf[nh * 4 + 2], bf[nh * 4 + 3],
                           bB + (uint32_t)(nh * 16 * (PITCH * 2)) + ks * 32);
                #pragma unroll
                for (int mi = 0; mi < 4; mi++)
                    #pragma unroll
                    for (int ni = 0; ni < 4; ni++)
                        mma16816(acc[mi][ni],
                                 af[mi][0], af[mi][1], af[mi][2], af[mi][3],
                                 bf[ni * 2], bf[ni * 2 + 1]);
            }
        }
    }

    // ---- epilogue ----
    // acc[mi][ni]: c0=C[m][n], c1=C[m][n+1], c2=C[m+8][n], c3=C[m+8][n+1]
    // m = bm+wm+mi*16+(lane>>2), n = bn+wn+ni*8+(lane&3)*2
    #pragma unroll
    for (int mi = 0; mi < 4; mi++) {
        const int m0 = bm + wm + mi * 16 + (lane >> 2);
        #pragma unroll
        for (int half = 0; half < 2; half++) {
            const size_t row = (size_t)(m0 + half * 8) * N;
            #pragma unroll
            for (int ni = 0; ni < 4; ni++) {
                const int n0 = bn + wn + ni * 8 + (lane & 3) * 2;
                float2 v;
                v.x = acc[mi][ni][half * 2 + 0];
                v.y = acc[mi][ni][half * 2 + 1];
                if (bias) { v.x += bias[n0]; v.y += bias[n0 + 1]; }
                if (resid) {
                    const float2 r = *reinterpret_cast<const float2*>(resid + row + n0);
                    v.x += r.x; v.y += r.y;
                }
                *reinterpret_cast<float2*>(C + row + n0) = v;
            }
        }
    }
}

// ------------------------------ helpers ------------------------------------
__device__ __forceinline__ float sigmoidf_(float x) { return 1.f / (1.f + expf(-x)); }
__device__ __forceinline__ float gelu_exact(float x) {
    return 0.5f * x * (1.f + erff(x * 0.70710678118654752440f));
}

// ------------------------------ rmsnorm ------------------------------------
__global__ void rmsnorm_kernel(const float* __restrict__ x,
                               const float* __restrict__ gamma,
                               float* __restrict__ out)
{
    const int row = blockIdx.x;
    const int tid = threadIdx.x;
    const float4 v = reinterpret_cast<const float4*>(x + (size_t)row * DIM)[tid];
    float ss = v.x*v.x + v.y*v.y + v.z*v.z + v.w*v.w;
    #pragma unroll
    for (int o = 16; o > 0; o >>= 1) ss += __shfl_xor_sync(0xffffffffu, ss, o);
    __shared__ float red[8];
    if ((tid & 31) == 0) red[tid >> 5] = ss;
    __syncthreads();
    float tot = red[0] + red[1] + red[2] + red[3] + red[4] + red[5] + red[6] + red[7];
    const float scale = sqrtf((float)DIM / tot);
    const float4 g = reinterpret_cast<const float4*>(gamma)[tid];
    float4 o4;
    o4.x = v.x * g.x * scale;
    o4.y = v.y * g.y * scale;
    o4.z = v.z * g.z * scale;
    o4.w = v.w * g.w * scale;
    reinterpret_cast<float4*>(out + (size_t)row * DIM)[tid] = o4;
}

// -------------------------- depthwise causal conv ---------------------------
__global__ void conv_kernel(const float* __restrict__ z,
                            const float* __restrict__ conv_w,
                            const float* __restrict__ conv_b,
                            float* __restrict__ out)
{
    const int idx = blockIdx.x * blockDim.x + threadIdx.x;
    const int c   = idx & (HID - 1);
    const int row = idx >> 11;
    const int t   = row & (TLEN - 1);
    const float* zc = z + (size_t)row * H2 + HID + c;
    const float w0 = conv_w[c * KCONV + 0];
    const float w1 = conv_w[c * KCONV + 1];
    const float w2 = conv_w[c * KCONV + 2];
    const float w3 = conv_w[c * KCONV + 3];
    float acc = conv_b[c] + w3 * zc[0];
    if (t >= 1) acc = fmaf(w2, zc[-(ptrdiff_t)H2],      acc);
    if (t >= 2) acc = fmaf(w1, zc[-2 * (ptrdiff_t)H2],  acc);
    if (t >= 3) acc = fmaf(w0, zc[-3 * (ptrdiff_t)H2],  acc);
    out[(size_t)row * HID + c] = acc;
}

// --------------------------- scan phase 1 -----------------------------------
__global__ void scan_phase1(const float* __restrict__ g,
                            const float* __restrict__ xc,
                            const float* __restrict__ forget_base,
                            float* __restrict__ z_P,
                            float* __restrict__ L_out)
{
    const int idx = blockIdx.x * blockDim.x + threadIdx.x;
    const int c   = idx & (HID - 1);
    const int seg = (idx >> 11) & (NSEG - 1);
    const int b   = idx >> 15;

    const float coef = -8.0f * log1pf(expf(forget_base[c]));
    float P = 1.f, L = 0.f;
    const size_t row0 = (size_t)b * TLEN + seg * SEG;
    for (int i = 0; i < SEG; i++) {
        const size_t row = row0 + i;
        const float f   = g[row * H2 + c];
        const float ip  = g[row * H2 + HID + c];
        const float xcv = xc[row * HID + c];
        const float alpha = expf(coef * sigmoidf_(f));
        const float beta  = sqrtf(1.f - alpha * alpha + 1e-6f);
        const float xs    = beta * sigmoidf_(ip) * xcv;
        P *= alpha;
        L = fmaf(alpha, L, xs);
        z_P[row * H2 + HID + c] = P;
        L_out[row * HID + c]    = L;
    }
}

// --------------------------- scan phase 2 -----------------------------------
__global__ void scan_phase2(const float* __restrict__ z_P,
                            const float* __restrict__ L,
                            float* __restrict__ h0buf)
{
    const int idx = blockIdx.x * blockDim.x + threadIdx.x;
    const int c = idx & (HID - 1);
    const int b = idx >> 11;
    float h0 = 0.f;
    #pragma unroll
    for (int s = 0; s < NSEG; s++) {
        h0buf[((size_t)b * NSEG + s) * HID + c] = h0;
        const size_t last = (size_t)b * TLEN + s * SEG + (SEG - 1);
        h0 = fmaf(z_P[last * H2 + HID + c], h0, L[last * HID + c]);
    }
}

// --------------------- scan phase 3 (+ gelu(gate) * h) ----------------------
__global__ void scan_phase3(const float* __restrict__ z,
                            const float* __restrict__ h0buf,
                            float* __restrict__ hL)
{
    const int idx = blockIdx.x * blockDim.x + threadIdx.x;
    const int c   = idx & (HID - 1);
    const int row = idx >> 11;
    const int t   = row & (TLEN - 1);
    const int b   = row >> 11;
    const int seg = t >> 7;
    const float L    = hL[idx];
    const float P    = z[(size_t)row * H2 + HID + c];
    const float h0   = h0buf[((size_t)b * NSEG + seg) * HID + c];
    const float h    = fmaf(P, h0, L);
    const float gate = z[(size_t)row * H2 + c];
    hL[idx] = gelu_exact(gate) * h;
}

// ---------------------------- MLP gating ------------------------------------
__global__ void mlp_gate_kernel(const float* __restrict__ gz, float* __restrict__ m)
{
    const int idx = blockIdx.x * blockDim.x + threadIdx.x;
    const int c   = idx & (GHID - 1);
    const int row = idx >> 11;
    const float mg = gz[(size_t)row * H2 + c];
    const float mx = gz[(size_t)row * H2 + GHID + c];
    m[idx] = gelu_exact(mg) * mx;
}

// ------------------------------ launcher ------------------------------------
extern "C" void kernel_launch(void* const* d_in, const int* in_sizes, int n_in,
                              void* d_out, int out_size)
{
    const float* x           = (const float*)d_in[0];
    const float* W_in        = (const float*)d_in[1];
    const float* conv_w      = (const float*)d_in[2];
    const float* conv_b      = (const float*)d_in[3];
    const float* W_gates     = (const float*)d_in[4];
    const float* b_gates     = (const float*)d_in[5];
    const float* forget_base = (const float*)d_in[6];
    const float* W_out       = (const float*)d_in[7];
    const float* gamma1      = (const float*)d_in[8];
    const float* gamma2      = (const float*)d_in[9];
    const float* W_grow      = (const float*)d_in[10];
    const float* W_shrink    = (const float*)d_in[11];
    float* out = (float*)d_out;

    float *pxn, *pz, *pxc, *pg, *ph, *ph0;
    cudaGetSymbolAddress((void**)&pxn, g_xn);
    cudaGetSymbolAddress((void**)&pz,  g_z);
    cudaGetSymbolAddress((void**)&pxc, g_xc);
    cudaGetSymbolAddress((void**)&pg,  g_g);
    cudaGetSymbolAddress((void**)&ph,  g_h);
    cudaGetSymbolAddress((void**)&ph0, g_h0);

    const dim3 blk(256);

    // 1. xn = rmsnorm(x, gamma1)
    rmsnorm_kernel<<<MROWS, blk>>>(x, gamma1, pxn);

    // 2. z = xn @ W_in^T   [8192,4096]
    mma_gemm<<<dim3(H2 / TN, MROWS / TM), blk>>>(pxn, W_in, nullptr, nullptr, pz,
                                                 MROWS, H2, DIM);

    // 3. xc = depthwise causal conv + bias
    conv_kernel<<<(MROWS * HID) / 256, blk>>>(pz, conv_w, conv_b, pxc);

    // 4. g = xc @ W_gates^T + b_gates   [8192,4096]
    mma_gemm<<<dim3(H2 / TN, MROWS / TM), blk>>>(pxc, W_gates, b_gates, nullptr, pg,
                                                 MROWS, H2, HID);

    // 5. chunked linear recurrence
    scan_phase1<<<(BATCH * NSEG * HID) / 256, blk>>>(pg, pxc, forget_base, pz, ph);
    scan_phase2<<<(BATCH * HID) / 256, blk>>>(pz, ph, ph0);
    scan_phase3<<<(MROWS * HID) / 256, blk>>>(pz, ph0, ph);

    // 6. x2 = x + (gelu(gate)*h) @ W_out^T  -> d_out
    mma_gemm<<<dim3(DIM / TN, MROWS / TM), blk>>>(ph, W_out, nullptr, x, out,
                                                  MROWS, DIM, HID);

    // 7. xn2 = rmsnorm(x2, gamma2)
    rmsnorm_kernel<<<MROWS, blk>>>(out, gamma2, pxn);

    // 8. gz = xn2 @ W_grow^T   [8192,4096]
    mma_gemm<<<dim3(H2 / TN, MROWS / TM), blk>>>(pxn, W_grow, nullptr, nullptr, pz,
                                                 MROWS, H2, DIM);

    // 9. m = gelu(mgate) * mx
    mlp_gate_kernel<<<(MROWS * GHID) / 256, blk>>>(pz, pxc);

    // 10. out = x2 + m @ W_shrink^T  (accumulate into d_out)
    mma_gemm<<<dim3(DIM / TN, MROWS / TM), blk>>>(pxc, W_shrink, nullptr, out, out,
                                                  MROWS, DIM, HID);
}